// round 8
// baseline (speedup 1.0000x reference)
#include <cuda_runtime.h>
#include <cuda_bf16.h>
#include <cstdint>

// ============================================================================
// LateInteractionScorer: scores[b] = sum_q max_d ( <Q[b,q], D[b,d]> + (1-mask)*(-1e30) )
// Q: [64,32,128] f32, D: [64,4096,128] f32, mask: [64,4096] i32 -> out [64] f32
//
// Base-ISA tensor path (mma.sync.m16n8k16 bf16; tcgen05 rejected at sm_103
// base target). DRAM-bound problem: 134 MB doc stream, ~17 us floor.
//
// R8: cp.async (LDGSTS) double-buffered SMEM staging so in-flight DRAM bytes
// are decoupled from register count (R7 was latency-limited at 55% DRAM).
// 576B row stride in SMEM -> conflict-free LDS.128 consumption.
// ============================================================================

static constexpr int BATCH = 64;
static constexpr int QLEN  = 32;
static constexpr int DLEN  = 4096;
static constexpr int HD    = 128;

static constexpr int SPLITS = 16;
static constexpr int DOCS_PER_SPLIT = DLEN / SPLITS;   // 256
static constexpr int THREADS = 128;
static constexpr int WARPS   = THREADS / 32;           // 4
static constexpr int STAGE_DOCS = 64;                  // docs per pipeline stage
static constexpr int STAGES = DOCS_PER_SPLIT / STAGE_DOCS;  // 4

static constexpr int ROW_BYTES = 576;                  // 512 + 64: LDS.128 conflict-free
static constexpr int BUF_BYTES = STAGE_DOCS * ROW_BYTES;    // 36864
static constexpr int SMEM_DYN  = 2 * BUF_BYTES;        // 73728

static constexpr float NEGV = -1e30f;

// Cross-CTA scratch (zero-init at load; last CTA per batch resets after use,
// so graph replays see identical initial state). ordenc(x) > 0 for all floats,
// so 0 is the atomicMax identity.
__device__ unsigned g_qmax[BATCH * QLEN];
__device__ int      g_count[BATCH];

__device__ __forceinline__ unsigned ordenc(float f) {
    unsigned b = __float_as_uint(f);
    return (b & 0x80000000u) ? ~b : (b | 0x80000000u);
}
__device__ __forceinline__ float orddec(unsigned o) {
    unsigned b = (o & 0x80000000u) ? (o & 0x7FFFFFFFu) : ~o;
    return __uint_as_float(b);
}

__device__ __forceinline__ uint32_t packbf(float lo, float hi) {
    __nv_bfloat162 h = __floats2bfloat162_rn(lo, hi);
    return *reinterpret_cast<uint32_t*>(&h);
}

__device__ __forceinline__ void mma16816(float* c, const uint32_t* a, const uint32_t* b) {
    asm volatile(
        "mma.sync.aligned.m16n8k16.row.col.f32.bf16.bf16.f32 "
        "{%0,%1,%2,%3}, {%4,%5,%6,%7}, {%8,%9}, {%0,%1,%2,%3};"
        : "+f"(c[0]), "+f"(c[1]), "+f"(c[2]), "+f"(c[3])
        : "r"(a[0]), "r"(a[1]), "r"(a[2]), "r"(a[3]),
          "r"(b[0]), "r"(b[1]));
}

__device__ __forceinline__ uint32_t smem_u32(const void* p) {
    uint32_t a;
    asm("{ .reg .u64 t; cvta.to.shared.u64 t, %1; cvt.u32.u64 %0, t; }"
        : "=r"(a) : "l"(p));
    return a;
}

__device__ __forceinline__ void cp_async16(uint32_t dst, const void* src) {
    asm volatile("cp.async.cg.shared.global [%0], [%1], 16;"
                 :: "r"(dst), "l"(src) : "memory");
}
#define CP_COMMIT()  asm volatile("cp.async.commit_group;" ::: "memory")
#define CP_WAIT(N)   asm volatile("cp.async.wait_group %0;" :: "n"(N) : "memory")

// ---------------------------------------------------------------------------
// Fused kernel: grid (SPLITS, BATCH), 128 threads
// ---------------------------------------------------------------------------
__global__ __launch_bounds__(THREADS)
void li_score_kernel(const float* __restrict__ qv,
                     const float* __restrict__ dv,
                     const int*   __restrict__ mask,
                     float*       __restrict__ out) {
    extern __shared__ char stage_sm[];
    __shared__ float red[WARPS * QLEN];
    __shared__ int   s_last;

    const int tid  = threadIdx.x;
    const int wid  = tid >> 5;
    const int lane = tid & 31;
    const int g    = lane >> 2;   // groupID
    const int tig  = lane & 3;    // thread-in-group

    const int b     = blockIdx.y;
    const int split = blockIdx.x;

    const float* Qb = qv + (size_t)b * QLEN * HD;
    const float* Ds = dv + ((size_t)b * DLEN + (size_t)split * DOCS_PER_SPLIT) * HD;
    const int*   Mb = mask + (size_t)b * DLEN + split * DOCS_PER_SPLIT;

    const uint32_t smbase = smem_u32(stage_sm);

    // ---- Kick off stage 0 prefetch immediately (before Q prologue) ----
    {
#pragma unroll
        for (int i = 0; i < (STAGE_DOCS * 32) / THREADS; i++) {
            int c = tid + i * THREADS;        // 16B chunk id, 0..2047
            int r = c >> 5, col = c & 31;
            cp_async16(smbase + r * ROW_BYTES + col * 16,
                       (const char*)(Ds + (size_t)r * HD) + col * 16);
        }
        CP_COMMIT();
    }

    // ---- Preload B fragments (queries) into registers ----
    // K-slot permutation: lane tig supplies physical dims {tig*4..tig*4+3}
    // into MMA k-slots {tig*2, tig*2+1, tig*2+8, tig*2+9}; A uses the same
    // permutation so the contraction is invariant.
    uint32_t Bf[4][8][2];
#pragma unroll
    for (int n = 0; n < 4; n++) {
        const float* qrow = Qb + (n * 8 + g) * HD;
#pragma unroll
        for (int k = 0; k < 8; k++) {
            float4 f = *(const float4*)(qrow + k * 16 + tig * 4);
            Bf[n][k][0] = packbf(f.x, f.y);
            Bf[n][k][1] = packbf(f.z, f.w);
        }
    }

    float qmax[8];
#pragma unroll
    for (int i = 0; i < 8; i++) qmax[i] = -3.0e38f;

    for (int s = 0; s < STAGES; s++) {
        // Prefetch next stage into the other buffer, then wait for stage s.
        if (s + 1 < STAGES) {
            const float* src = Ds + (size_t)(s + 1) * STAGE_DOCS * HD;
            const uint32_t dbase = smbase + ((s + 1) & 1) * BUF_BYTES;
#pragma unroll
            for (int i = 0; i < (STAGE_DOCS * 32) / THREADS; i++) {
                int c = tid + i * THREADS;
                int r = c >> 5, col = c & 31;
                cp_async16(dbase + r * ROW_BYTES + col * 16,
                           (const char*)(src + (size_t)r * HD) + col * 16);
            }
            CP_COMMIT();
            CP_WAIT(1);
        } else {
            CP_WAIT(0);
        }
        __syncthreads();

        // ---- Consume stage s: each warp does 16 docs x 32 queries ----
        const int dtile = s * STAGE_DOCS;
        const int r0 = dtile + wid * 16 + g;
        const int r1 = r0 + 8;
        const float adj0 = Mb[r0] ? 0.0f : NEGV;
        const float adj1 = Mb[r1] ? 0.0f : NEGV;

        const char* abase = stage_sm + (s & 1) * BUF_BYTES + (wid * 16) * ROW_BYTES;
        const char* arow0 = abase + g * ROW_BYTES + tig * 16;
        const char* arow1 = arow0 + 8 * ROW_BYTES;

        float acc[4][4];
#pragma unroll
        for (int n = 0; n < 4; n++)
#pragma unroll
            for (int i = 0; i < 4; i++) acc[n][i] = 0.0f;

#pragma unroll
        for (int k = 0; k < 8; k++) {
            float4 fa0 = *(const float4*)(arow0 + k * 64);
            float4 fa1 = *(const float4*)(arow1 + k * 64);
            uint32_t A[4];
            A[0] = packbf(fa0.x, fa0.y);
            A[1] = packbf(fa1.x, fa1.y);
            A[2] = packbf(fa0.z, fa0.w);
            A[3] = packbf(fa1.z, fa1.w);
#pragma unroll
            for (int n = 0; n < 4; n++) mma16816(acc[n], A, Bf[n][k]);
        }

#pragma unroll
        for (int n = 0; n < 4; n++) {
            qmax[n * 2 + 0] = fmaxf(qmax[n * 2 + 0],
                                    fmaxf(acc[n][0] + adj0, acc[n][2] + adj1));
            qmax[n * 2 + 1] = fmaxf(qmax[n * 2 + 1],
                                    fmaxf(acc[n][1] + adj0, acc[n][3] + adj1));
        }
        __syncthreads();   // all warps done reading buf (s&1) before re-staging
    }

    // ---- Max over the 8 groupIDs (lane bits [2:5)) ----
#pragma unroll
    for (int i = 0; i < 8; i++) {
#pragma unroll
        for (int o = 4; o <= 16; o <<= 1)
            qmax[i] = fmaxf(qmax[i], __shfl_xor_sync(0xffffffffu, qmax[i], o));
    }
    if (g == 0) {  // lanes 0..3, tig = lane
#pragma unroll
        for (int n = 0; n < 4; n++) {
            red[wid * QLEN + n * 8 + tig * 2 + 0] = qmax[n * 2 + 0];
            red[wid * QLEN + n * 8 + tig * 2 + 1] = qmax[n * 2 + 1];
        }
    }
    __syncthreads();

    // ---- Max across warps, fold into per-batch global scratch ----
    if (tid < QLEN) {
        float v = red[tid];
#pragma unroll
        for (int w = 1; w < WARPS; w++) v = fmaxf(v, red[w * QLEN + tid]);
        atomicMax(&g_qmax[b * QLEN + tid], ordenc(v));
    }
    __threadfence();

    // ---- Last CTA per batch: sum over q, write out, reset scratch ----
    if (tid == 0)
        s_last = (atomicAdd(&g_count[b], 1) == SPLITS - 1) ? 1 : 0;
    __syncthreads();

    if (s_last) {
        if (tid < QLEN) {
            unsigned o = atomicMax(&g_qmax[b * QLEN + tid], 0u);
            float v = orddec(o);
#pragma unroll
            for (int off = 16; off > 0; off >>= 1)
                v += __shfl_xor_sync(0xffffffffu, v, off);
            if (tid == 0) out[b] = v;
            g_qmax[b * QLEN + tid] = 0u;   // reset for next graph replay
        }
        if (tid == 0) g_count[b] = 0;
    }
}

// ---------------------------------------------------------------------------
extern "C" void kernel_launch(void* const* d_in, const int* in_sizes, int n_in,
                              void* d_out, int out_size) {
    const float* qv   = (const float*)d_in[0];   // [64,32,128] f32
    const float* dv   = (const float*)d_in[1];   // [64,4096,128] f32
    const int*   mask = (const int*)d_in[2];     // [64,4096] i32
    float* out = (float*)d_out;                  // [64] f32

    cudaFuncSetAttribute(li_score_kernel,
                         cudaFuncAttributeMaxDynamicSharedMemorySize, SMEM_DYN);

    dim3 grid(SPLITS, BATCH);
    li_score_kernel<<<grid, THREADS, SMEM_DYN>>>(qv, dv, mask, out);
}

// round 9
// speedup vs baseline: 1.1781x; 1.1781x over previous
#include <cuda_runtime.h>
#include <cuda_bf16.h>
#include <cstdint>

// ============================================================================
// LateInteractionScorer: scores[b] = sum_q max_d ( <Q[b,q], D[b,d]> + (1-mask)*(-1e30) )
// Q: [64,32,128] f32, D: [64,4096,128] f32, mask: [64,4096] i32 -> out [64] f32
//
// Base-ISA tensor path (mma.sync.m16n8k16 bf16). DRAM-bound: 134 MB doc
// stream, ~17-20 us floor.
//
// R9: R7's direct-LDG streaming loop, but query B-fragments live in an 8 KB
// SMEM table (conflict-free LDS.128) instead of 64 regs/thread. Frees regs ->
// 3 CTAs/SM occupancy -> more in-flight DRAM loads. 1024 CTAs for balance.
// ============================================================================

static constexpr int BATCH = 64;
static constexpr int QLEN  = 32;
static constexpr int DLEN  = 4096;
static constexpr int HD    = 128;

static constexpr int SPLITS = 16;
static constexpr int DOCS_PER_SPLIT = DLEN / SPLITS;   // 256
static constexpr int THREADS = 256;
static constexpr int WARPS   = THREADS / 32;           // 8
static constexpr int DOCS_PER_ITER = WARPS * 16;       // 128
static constexpr int ITERS = DOCS_PER_SPLIT / DOCS_PER_ITER;  // 2

static constexpr float NEGV = -1e30f;

// Cross-CTA scratch (zero-init at load; last CTA per batch resets after use,
// so graph replays see identical initial state). ordenc(x) > 0 for all floats,
// so 0 is the atomicMax identity.
__device__ unsigned g_qmax[BATCH * QLEN];
__device__ int      g_count[BATCH];

__device__ __forceinline__ unsigned ordenc(float f) {
    unsigned b = __float_as_uint(f);
    return (b & 0x80000000u) ? ~b : (b | 0x80000000u);
}
__device__ __forceinline__ float orddec(unsigned o) {
    unsigned b = (o & 0x80000000u) ? (o & 0x7FFFFFFFu) : ~o;
    return __uint_as_float(b);
}

__device__ __forceinline__ uint32_t packbf(float lo, float hi) {
    __nv_bfloat162 h = __floats2bfloat162_rn(lo, hi);
    return *reinterpret_cast<uint32_t*>(&h);
}

__device__ __forceinline__ void mma16816(float* c, const uint32_t* a, const uint32_t* b) {
    asm volatile(
        "mma.sync.aligned.m16n8k16.row.col.f32.bf16.bf16.f32 "
        "{%0,%1,%2,%3}, {%4,%5,%6,%7}, {%8,%9}, {%0,%1,%2,%3};"
        : "+f"(c[0]), "+f"(c[1]), "+f"(c[2]), "+f"(c[3])
        : "r"(a[0]), "r"(a[1]), "r"(a[2]), "r"(a[3]),
          "r"(b[0]), "r"(b[1]));
}

// ---------------------------------------------------------------------------
// Fused kernel: grid (SPLITS, BATCH), 256 threads, min 3 CTAs/SM
// ---------------------------------------------------------------------------
__global__ __launch_bounds__(THREADS, 3)
void li_score_kernel(const float* __restrict__ qv,
                     const float* __restrict__ dv,
                     const int*   __restrict__ mask,
                     float*       __restrict__ out) {
    // Q B-fragment table: [k 0..8)][half 0..2)][lane 0..32)][4 x u32]
    // half0 = n-chunks {0,1}, half1 = n-chunks {2,3}.
    // Lane reads 16 B at stride 16 -> conflict-free LDS.128.
    __shared__ alignas(16) uint32_t qsm[8 * 2 * 32 * 4];   // 8 KB
    __shared__ float red[WARPS * QLEN];
    __shared__ int   s_last;

    const int tid  = threadIdx.x;
    const int wid  = tid >> 5;
    const int lane = tid & 31;
    const int g    = lane >> 2;   // groupID
    const int tig  = lane & 3;    // thread-in-group

    const int b     = blockIdx.y;
    const int split = blockIdx.x;

    const float* Qb = qv + (size_t)b * QLEN * HD;
    const float* Ds = dv + ((size_t)b * DLEN + (size_t)split * DOCS_PER_SPLIT) * HD;
    const int*   Mb = mask + (size_t)b * DLEN + split * DOCS_PER_SPLIT;

    // ---- Prologue: build B fragments in SMEM (each thread owns one (k,l)) ----
    // K-slot permutation: lane tig supplies physical dims {tig*4..tig*4+3} into
    // MMA k-slots {tig*2, tig*2+1, tig*2+8, tig*2+9}; the A side uses the same
    // permutation, so the contraction is invariant.
    {
        const int k = tid >> 5;       // 0..7
        const int l = tid & 31;
        const int lg = l >> 2, lt = l & 3;
        const int c0 = k * 16 + lt * 4;
        uint4 h0, h1;
        {
            float4 f0 = *(const float4*)(Qb + (0 * 8 + lg) * HD + c0);
            float4 f1 = *(const float4*)(Qb + (1 * 8 + lg) * HD + c0);
            h0.x = packbf(f0.x, f0.y); h0.y = packbf(f0.z, f0.w);
            h0.z = packbf(f1.x, f1.y); h0.w = packbf(f1.z, f1.w);
        }
        {
            float4 f2 = *(const float4*)(Qb + (2 * 8 + lg) * HD + c0);
            float4 f3 = *(const float4*)(Qb + (3 * 8 + lg) * HD + c0);
            h1.x = packbf(f2.x, f2.y); h1.y = packbf(f2.z, f2.w);
            h1.z = packbf(f3.x, f3.y); h1.w = packbf(f3.z, f3.w);
        }
        *(uint4*)(qsm + (k * 2 + 0) * 128 + l * 4) = h0;
        *(uint4*)(qsm + (k * 2 + 1) * 128 + l * 4) = h1;
    }
    __syncthreads();

    const uint4* qtab = (const uint4*)qsm;   // [k*2+half]*32 + lane

    float qmax[8];
#pragma unroll
    for (int i = 0; i < 8; i++) qmax[i] = -3.0e38f;

#pragma unroll
    for (int it = 0; it < ITERS; it++) {
        const int dtile = it * DOCS_PER_ITER + wid * 16;
        const int r0 = dtile + g;
        const int r1 = r0 + 8;
        const float adj0 = Mb[r0] ? 0.0f : NEGV;
        const float adj1 = Mb[r1] ? 0.0f : NEGV;
        const float* row0 = Ds + (size_t)r0 * HD + tig * 4;
        const float* row1 = Ds + (size_t)r1 * HD + tig * 4;

        float acc[4][4];
#pragma unroll
        for (int n = 0; n < 4; n++)
#pragma unroll
            for (int i = 0; i < 4; i++) acc[n][i] = 0.0f;

#pragma unroll
        for (int k = 0; k < 8; k++) {
            float4 fa0 = *(const float4*)(row0 + k * 16);   // one LDG.128 per row
            float4 fa1 = *(const float4*)(row1 + k * 16);
            uint4 h0 = qtab[(k * 2 + 0) * 32 + lane];       // LDS.128, n-chunks 0,1
            uint4 h1 = qtab[(k * 2 + 1) * 32 + lane];       // LDS.128, n-chunks 2,3
            uint32_t A[4];
            A[0] = packbf(fa0.x, fa0.y);
            A[1] = packbf(fa1.x, fa1.y);
            A[2] = packbf(fa0.z, fa0.w);
            A[3] = packbf(fa1.z, fa1.w);
            uint32_t B0[2] = {h0.x, h0.y}, B1[2] = {h0.z, h0.w};
            uint32_t B2[2] = {h1.x, h1.y}, B3[2] = {h1.z, h1.w};
            mma16816(acc[0], A, B0);
            mma16816(acc[1], A, B1);
            mma16816(acc[2], A, B2);
            mma16816(acc[3], A, B3);
        }

        // D frag: c0=D[g][tig*2] c1=D[g][tig*2+1] c2=D[g+8][tig*2] c3=D[g+8][tig*2+1]
#pragma unroll
        for (int n = 0; n < 4; n++) {
            qmax[n * 2 + 0] = fmaxf(qmax[n * 2 + 0],
                                    fmaxf(acc[n][0] + adj0, acc[n][2] + adj1));
            qmax[n * 2 + 1] = fmaxf(qmax[n * 2 + 1],
                                    fmaxf(acc[n][1] + adj0, acc[n][3] + adj1));
        }
    }

    // ---- Max over the 8 groupIDs (lane bits [2:5)) ----
#pragma unroll
    for (int i = 0; i < 8; i++) {
#pragma unroll
        for (int o = 4; o <= 16; o <<= 1)
            qmax[i] = fmaxf(qmax[i], __shfl_xor_sync(0xffffffffu, qmax[i], o));
    }
    if (g == 0) {  // lanes 0..3, tig = lane
#pragma unroll
        for (int n = 0; n < 4; n++) {
            red[wid * QLEN + n * 8 + tig * 2 + 0] = qmax[n * 2 + 0];
            red[wid * QLEN + n * 8 + tig * 2 + 1] = qmax[n * 2 + 1];
        }
    }
    __syncthreads();

    // ---- Max across warps, fold into per-batch global scratch ----
    if (tid < QLEN) {
        float v = red[tid];
#pragma unroll
        for (int w = 1; w < WARPS; w++) v = fmaxf(v, red[w * QLEN + tid]);
        atomicMax(&g_qmax[b * QLEN + tid], ordenc(v));
    }
    __threadfence();

    // ---- Last CTA per batch: sum over q, write out, reset scratch ----
    if (tid == 0)
        s_last = (atomicAdd(&g_count[b], 1) == SPLITS - 1) ? 1 : 0;
    __syncthreads();

    if (s_last) {
        if (tid < QLEN) {
            unsigned o = atomicMax(&g_qmax[b * QLEN + tid], 0u);
            float v = orddec(o);
#pragma unroll
            for (int off = 16; off > 0; off >>= 1)
                v += __shfl_xor_sync(0xffffffffu, v, off);
            if (tid == 0) out[b] = v;
            g_qmax[b * QLEN + tid] = 0u;   // reset for next graph replay
        }
        if (tid == 0) g_count[b] = 0;
    }
}

// ---------------------------------------------------------------------------
extern "C" void kernel_launch(void* const* d_in, const int* in_sizes, int n_in,
                              void* d_out, int out_size) {
    const float* qv   = (const float*)d_in[0];   // [64,32,128] f32
    const float* dv   = (const float*)d_in[1];   // [64,4096,128] f32
    const int*   mask = (const int*)d_in[2];     // [64,4096] i32
    float* out = (float*)d_out;                  // [64] f32

    dim3 grid(SPLITS, BATCH);
    li_score_kernel<<<grid, THREADS>>>(qv, dv, mask, out);
}